// round 4
// baseline (speedup 1.0000x reference)
#include <cuda_runtime.h>

// Problem constants
#define D_MODEL 1024
#define NH      16
#define DH      64
#define KEIG    16
#define M_TOK   16384          // B * N = 4 * 4096
#define NC      3072           // 3 * NH * DH (fused Qf|Kf|Vf columns)
#define KDIM    1024

// GEMM tiling
#define BM 128
#define BN 128
#define BK 16

// Device scratch (allocation-free rule: static __device__ arrays)
__device__ float g_Wc[(size_t)KDIM * NC];          // transformed fused weights  (12.6 MB)
__device__ float g_bc[NC];                          // transformed fused bias
__device__ float g_QKVf[(size_t)M_TOK * NC];        // Qf|Kf|Vf per token         (201 MB)

// ---------------------------------------------------------------------------
// Kernel A1: fold eigenvectors + filter weights into the projection weights.
// Wc[r, s*1024 + k*64 + d] = fw[k] * sum_h E[h,k] * Ws[r, h*64 + d]
// ---------------------------------------------------------------------------
__global__ __launch_bounds__(256)
void k_transform_w(const float* __restrict__ Wq,
                   const float* __restrict__ Wk,
                   const float* __restrict__ Wv,
                   const float* __restrict__ E,
                   const float* __restrict__ fw)
{
    int idx = blockIdx.x * blockDim.x + threadIdx.x;
    if (idx >= KDIM * NC) return;
    int r = idx / NC;
    int j = idx - r * NC;
    int s = j >> 10;          // 0 = Q, 1 = K, 2 = V
    int c = j & 1023;
    int k = c >> 6;
    int d = c & 63;
    const float* W = (s == 0) ? Wq : (s == 1) ? Wk : Wv;
    const float* Wrow = W + (size_t)r * (NH * DH) + d;
    float acc = 0.f;
#pragma unroll
    for (int h = 0; h < NH; h++)
        acc = fmaf(__ldg(&E[h * KEIG + k]), __ldg(&Wrow[h * DH]), acc);
    g_Wc[idx] = acc * __ldg(&fw[k]);
}

__global__ void k_transform_b(const float* __restrict__ bq,
                              const float* __restrict__ bk,
                              const float* __restrict__ bv,
                              const float* __restrict__ E,
                              const float* __restrict__ fw)
{
    int j = blockIdx.x * blockDim.x + threadIdx.x;
    if (j >= NC) return;
    int s = j >> 10;
    int c = j & 1023;
    int k = c >> 6;
    int d = c & 63;
    const float* b = (s == 0) ? bq : (s == 1) ? bk : bv;
    float acc = 0.f;
#pragma unroll
    for (int h = 0; h < NH; h++)
        acc = fmaf(E[h * KEIG + k], b[h * DH + d], acc);
    g_bc[j] = acc * fw[k];
}

// ---------------------------------------------------------------------------
// Kernel B: fused projection GEMM
//   QKVf[16384, 3072] = x[16384, 1024] @ Wc[1024, 3072] + bc
// 128x128 block tile, BK=16, 256 threads, 8x8 per thread, fp32 FMA.
// ---------------------------------------------------------------------------
__global__ __launch_bounds__(256, 2)
void k_gemm_qkv(const float* __restrict__ A)
{
    __shared__ float As[BK][BM];   // transposed A tile
    __shared__ float Bs[BK][BN];

    const int tid = threadIdx.x;
    const int bm  = blockIdx.y * BM;
    const int bn  = blockIdx.x * BN;

    // A-tile loader: 128x16 floats, each thread 2x float4 (transpose into As)
    const int aRow = tid >> 2;              // 0..63
    const int aCol = (tid & 3) << 2;        // 0,4,8,12
    // B-tile loader: 16x128 floats, each thread 2x float4
    const int bRow = tid >> 5;              // 0..7
    const int bCol = (tid & 31) << 2;       // 0..124

    const int ty = tid >> 4;                // 0..15
    const int tx = tid & 15;                // 0..15
    const int rowBase = ty * 8;
    const int colBase = tx * 8;

    const float* Aptr = A + (size_t)bm * KDIM;
    const float* Bptr = g_Wc + bn;

    float acc[8][8];
#pragma unroll
    for (int i = 0; i < 8; i++)
#pragma unroll
        for (int j = 0; j < 8; j++) acc[i][j] = 0.f;

    for (int k0 = 0; k0 < KDIM; k0 += BK) {
#pragma unroll
        for (int p = 0; p < 2; p++) {
            int r = aRow + p * 64;
            float4 v = *(const float4*)(Aptr + (size_t)r * KDIM + k0 + aCol);
            As[aCol + 0][r] = v.x;
            As[aCol + 1][r] = v.y;
            As[aCol + 2][r] = v.z;
            As[aCol + 3][r] = v.w;
        }
#pragma unroll
        for (int p = 0; p < 2; p++) {
            int r = bRow + p * 8;
            *(float4*)(&Bs[r][bCol]) = *(const float4*)(Bptr + (size_t)(k0 + r) * NC + bCol);
        }
        __syncthreads();

#pragma unroll
        for (int kk = 0; kk < BK; kk++) {
            float a[8], b[8];
            float4 a0 = *(const float4*)(&As[kk][rowBase]);
            float4 a1 = *(const float4*)(&As[kk][rowBase + 4]);
            float4 b0 = *(const float4*)(&Bs[kk][colBase]);
            float4 b1 = *(const float4*)(&Bs[kk][colBase + 4]);
            a[0]=a0.x; a[1]=a0.y; a[2]=a0.z; a[3]=a0.w;
            a[4]=a1.x; a[5]=a1.y; a[6]=a1.z; a[7]=a1.w;
            b[0]=b0.x; b[1]=b0.y; b[2]=b0.z; b[3]=b0.w;
            b[4]=b1.x; b[5]=b1.y; b[6]=b1.z; b[7]=b1.w;
#pragma unroll
            for (int i = 0; i < 8; i++)
#pragma unroll
                for (int j = 0; j < 8; j++)
                    acc[i][j] = fmaf(a[i], b[j], acc[i][j]);
        }
        __syncthreads();
    }

    // Epilogue: add bias, write out
#pragma unroll
    for (int i = 0; i < 8; i++) {
        float* Crow = g_QKVf + (size_t)(bm + rowBase + i) * NC + bn + colBase;
        const float* brow = g_bc + bn + colBase;
#pragma unroll
        for (int j = 0; j < 8; j += 4) {
            float4 v;
            v.x = acc[i][j + 0] + brow[j + 0];
            v.y = acc[i][j + 1] + brow[j + 1];
            v.z = acc[i][j + 2] + brow[j + 2];
            v.w = acc[i][j + 3] + brow[j + 3];
            *(float4*)(Crow + j) = v;
        }
    }
}

// ---------------------------------------------------------------------------
// Kernel C: per-token spectral attention + inverse eigen projection.
// One block per token (16384 blocks, 256 threads).
// ---------------------------------------------------------------------------
__global__ __launch_bounds__(256)
void k_attn(const float* __restrict__ E, float* __restrict__ out)
{
    __shared__ float sQ[KEIG][DH + 1];
    __shared__ float sK[KEIG][DH + 1];
    __shared__ float sV[KEIG][DH + 1];
    __shared__ float sS[KEIG][KEIG];      // scores -> attn weights
    __shared__ float sO[KEIG][DH + 1];    // out_f
    __shared__ float sE[NH * KEIG];

    const int tok = blockIdx.x;
    const int tid = threadIdx.x;
    const float* row = g_QKVf + (size_t)tok * NC;

    for (int i = tid; i < KEIG * DH; i += 256) {
        int k = i >> 6, d = i & 63;
        sQ[k][d] = row[i];
        sK[k][d] = row[1024 + i];
        sV[k][d] = row[2048 + i];
    }
    sE[tid] = E[tid];                      // NH*KEIG == 256 == blockDim
    __syncthreads();

    // scores[k][l] = (Qf[k] . Kf[l]) / sqrt(DH); one (k,l) per thread
    {
        int k = tid >> 4, l = tid & 15;
        float acc = 0.f;
#pragma unroll
        for (int d = 0; d < DH; d++)
            acc = fmaf(sQ[k][d], sK[l][d], acc);
        sS[k][l] = acc * 0.125f;           // 1/sqrt(64)
    }
    __syncthreads();

    // softmax over l for each row k (16 threads, 16 elems each)
    if (tid < KEIG) {
        int k = tid;
        float m = sS[k][0];
#pragma unroll
        for (int l = 1; l < KEIG; l++) m = fmaxf(m, sS[k][l]);
        float e[KEIG];
        float sum = 0.f;
#pragma unroll
        for (int l = 0; l < KEIG; l++) { e[l] = __expf(sS[k][l] - m); sum += e[l]; }
        float inv = 1.f / sum;
#pragma unroll
        for (int l = 0; l < KEIG; l++) sS[k][l] = e[l] * inv;
    }
    __syncthreads();

    // out_f[k][d] = sum_l attn[k][l] * Vf[l][d]
    for (int i = tid; i < KEIG * DH; i += 256) {
        int k = i >> 6, d = i & 63;
        float acc = 0.f;
#pragma unroll
        for (int l = 0; l < KEIG; l++)
            acc = fmaf(sS[k][l], sV[l][d], acc);
        sO[k][d] = acc;
    }
    __syncthreads();

    // out[h][d] = sum_k E[h,k] * out_f[k][d]
    float* orow = out + (size_t)tok * (NH * DH);
    for (int i = tid; i < NH * DH; i += 256) {
        int h = i >> 6, d = i & 63;
        float acc = 0.f;
#pragma unroll
        for (int k = 0; k < KEIG; k++)
            acc = fmaf(sE[h * KEIG + k], sO[k][d], acc);
        orow[i] = acc;
    }
}

// ---------------------------------------------------------------------------
extern "C" void kernel_launch(void* const* d_in, const int* in_sizes, int n_in,
                              void* d_out, int out_size)
{
    const float* x  = (const float*)d_in[0];
    const float* Wq = (const float*)d_in[1];
    const float* bq = (const float*)d_in[2];
    const float* Wk = (const float*)d_in[3];
    const float* bk = (const float*)d_in[4];
    const float* Wv = (const float*)d_in[5];
    const float* bv = (const float*)d_in[6];
    const float* E  = (const float*)d_in[7];
    const float* fw = (const float*)d_in[8];
    float* out = (float*)d_out;

    k_transform_w<<<(KDIM * NC + 255) / 256, 256>>>(Wq, Wk, Wv, E, fw);
    k_transform_b<<<(NC + 255) / 256, 256>>>(bq, bk, bv, E, fw);
    k_gemm_qkv<<<dim3(NC / BN, M_TOK / BM), 256>>>(x);
    k_attn<<<M_TOK, 256>>>(E, out);
}

// round 8
// speedup vs baseline: 2.6498x; 2.6498x over previous
#include <cuda_runtime.h>
#include <cuda_bf16.h>
#include <cstdint>

// Problem constants
#define D_MODEL 1024
#define NH      16
#define DH      64
#define KEIG    16
#define M_TOK   16384          // B * N = 4 * 4096
#define NC      3072           // 3 * NH * DH (fused Qf|Kf|Vf columns)
#define KDIM    1024

// GEMM tiling (mma.sync bf16 path)
#define BM 128
#define BN 128
#define BKC 32                 // K per chunk
#define NCH (KDIM / BKC)       // 32 chunks
#define STAGE 32768            // smem bytes per pipeline stage (4 tiles x 8KB)
#define GEMM_SMEM (2 * STAGE)  // 64 KB double buffered

// 64B-row swizzle: XOR 16B-vector index (bits 4:5) with row bits (bits 7:8)
#define SWZ64(o) ((uint32_t)(o) ^ ((((uint32_t)(o)) >> 3) & 0x30u))

// ---------------------------------------------------------------------------
// Device scratch (allocation-free rule: static __device__ arrays)
// ---------------------------------------------------------------------------
__device__ float         g_Wc[(size_t)KDIM * NC];    // eigen-folded weights fp32 [k][n]
__device__ float         g_bc[NC];                    // eigen-folded bias
__device__ float         g_QKVf[(size_t)M_TOK * NC]; // Qf|Kf|Vf per token
__device__ __nv_bfloat16 g_xh[(size_t)M_TOK * KDIM]; // x hi split  [m][k]
__device__ __nv_bfloat16 g_xl[(size_t)M_TOK * KDIM]; // x lo split
__device__ __nv_bfloat16 g_Wth[(size_t)NC * KDIM];   // W^T hi split [n][k]
__device__ __nv_bfloat16 g_Wtl[(size_t)NC * KDIM];   // W^T lo split

// ---------------------------------------------------------------------------
// PTX helpers (all baseline PTX — legal on non-'a' sm_103 target)
// ---------------------------------------------------------------------------
static __device__ __forceinline__ uint32_t smem_u32(const void* p) {
    uint32_t a;
    asm("{ .reg .u64 t; cvta.to.shared.u64 t, %1; cvt.u32.u64 %0, t; }"
        : "=r"(a) : "l"(p));
    return a;
}

static __device__ __forceinline__ void cp16(uint32_t saddr, const void* g) {
    asm volatile("cp.async.cg.shared.global [%0], [%1], 16;"
                 :: "r"(saddr), "l"(g));
}
static __device__ __forceinline__ void cp_commit() {
    asm volatile("cp.async.commit_group;" ::: "memory");
}
template <int N>
static __device__ __forceinline__ void cp_wait() {
    asm volatile("cp.async.wait_group %0;" :: "n"(N) : "memory");
}

static __device__ __forceinline__ void ldsm4(uint32_t* r, uint32_t addr) {
    asm volatile("ldmatrix.sync.aligned.m8n8.x4.shared.b16 {%0,%1,%2,%3}, [%4];"
                 : "=r"(r[0]), "=r"(r[1]), "=r"(r[2]), "=r"(r[3])
                 : "r"(addr));
}

static __device__ __forceinline__ void mma16816(float* d, const uint32_t* a,
                                                uint32_t b0, uint32_t b1) {
    asm volatile(
        "mma.sync.aligned.m16n8k16.row.col.f32.bf16.bf16.f32 "
        "{%0,%1,%2,%3}, {%4,%5,%6,%7}, {%8,%9}, {%0,%1,%2,%3};"
        : "+f"(d[0]), "+f"(d[1]), "+f"(d[2]), "+f"(d[3])
        : "r"(a[0]), "r"(a[1]), "r"(a[2]), "r"(a[3]), "r"(b0), "r"(b1));
}

// ---------------------------------------------------------------------------
// Kernel A1: fold eigenvectors + filter weights into fused weights (fp32)
// Wc[r, s*1024 + k*64 + d] = fw[k] * sum_h E[h,k] * Ws[r, h*64 + d]
// ---------------------------------------------------------------------------
__global__ __launch_bounds__(256)
void k_transform_w(const float* __restrict__ Wq,
                   const float* __restrict__ Wk,
                   const float* __restrict__ Wv,
                   const float* __restrict__ E,
                   const float* __restrict__ fw)
{
    int idx = blockIdx.x * blockDim.x + threadIdx.x;
    if (idx >= KDIM * NC) return;
    int r = idx / NC;
    int j = idx - r * NC;
    int s = j >> 10;
    int c = j & 1023;
    int k = c >> 6;
    int d = c & 63;
    const float* W = (s == 0) ? Wq : (s == 1) ? Wk : Wv;
    const float* Wrow = W + (size_t)r * (NH * DH) + d;
    float acc = 0.f;
#pragma unroll
    for (int h = 0; h < NH; h++)
        acc = fmaf(__ldg(&E[h * KEIG + k]), __ldg(&Wrow[h * DH]), acc);
    g_Wc[idx] = acc * __ldg(&fw[k]);
}

__global__ void k_transform_b(const float* __restrict__ bq,
                              const float* __restrict__ bk,
                              const float* __restrict__ bv,
                              const float* __restrict__ E,
                              const float* __restrict__ fw)
{
    int j = blockIdx.x * blockDim.x + threadIdx.x;
    if (j >= NC) return;
    int s = j >> 10;
    int c = j & 1023;
    int k = c >> 6;
    int d = c & 63;
    const float* b = (s == 0) ? bq : (s == 1) ? bk : bv;
    float acc = 0.f;
#pragma unroll
    for (int h = 0; h < NH; h++)
        acc = fmaf(E[h * KEIG + k], b[h * DH + d], acc);
    g_bc[j] = acc * fw[k];
}

// ---------------------------------------------------------------------------
// Kernel A2: split x into bf16 hi/lo (same [m][k] layout)
// ---------------------------------------------------------------------------
__global__ __launch_bounds__(256)
void k_split_x(const float* __restrict__ x)
{
    size_t i = ((size_t)blockIdx.x * 256 + threadIdx.x) * 4;
    float4 v = *(const float4*)(x + i);
    __nv_bfloat16 h0 = __float2bfloat16(v.x);
    __nv_bfloat16 h1 = __float2bfloat16(v.y);
    __nv_bfloat16 h2 = __float2bfloat16(v.z);
    __nv_bfloat16 h3 = __float2bfloat16(v.w);
    __nv_bfloat16 l0 = __float2bfloat16(v.x - __bfloat162float(h0));
    __nv_bfloat16 l1 = __float2bfloat16(v.y - __bfloat162float(h1));
    __nv_bfloat16 l2 = __float2bfloat16(v.z - __bfloat162float(h2));
    __nv_bfloat16 l3 = __float2bfloat16(v.w - __bfloat162float(h3));
    uint2 ph, pl;
    ph.x = ((uint32_t)__bfloat16_as_ushort(h1) << 16) | __bfloat16_as_ushort(h0);
    ph.y = ((uint32_t)__bfloat16_as_ushort(h3) << 16) | __bfloat16_as_ushort(h2);
    pl.x = ((uint32_t)__bfloat16_as_ushort(l1) << 16) | __bfloat16_as_ushort(l0);
    pl.y = ((uint32_t)__bfloat16_as_ushort(l3) << 16) | __bfloat16_as_ushort(l2);
    *(uint2*)(g_xh + i) = ph;
    *(uint2*)(g_xl + i) = pl;
}

// ---------------------------------------------------------------------------
// Kernel A3: transpose g_Wc [k][n] -> bf16 hi/lo [n][k] (smem-tiled)
// ---------------------------------------------------------------------------
__global__ __launch_bounds__(256)
void k_wsplit()
{
    __shared__ float t[32][33];
    int tx = threadIdx.x & 31;
    int ty = threadIdx.x >> 5;       // 0..7
    int n0 = blockIdx.x * 32;
    int k0 = blockIdx.y * 32;
#pragma unroll
    for (int i = 0; i < 32; i += 8)
        t[ty + i][tx] = g_Wc[(size_t)(k0 + ty + i) * NC + (n0 + tx)];
    __syncthreads();
#pragma unroll
    for (int i = 0; i < 32; i += 8) {
        int n = n0 + ty + i;
        int k = k0 + tx;
        float v = t[tx][ty + i];
        __nv_bfloat16 h = __float2bfloat16(v);
        __nv_bfloat16 l = __float2bfloat16(v - __bfloat162float(h));
        g_Wth[(size_t)n * KDIM + k] = h;
        g_Wtl[(size_t)n * KDIM + k] = l;
    }
}

// ---------------------------------------------------------------------------
// Kernel B: bf16-split GEMM via mma.sync (HMMA), cp.async double buffered.
//   QKVf[16384, 3072] = x @ Wc + bc  ==  xh*Wh + xh*Wl + xl*Wh (fp32 accum)
// CTA 128x128, 8 warps (2x4), warp tile 64x32, BK=32.
// smem per stage: Ah(8K) | Al(8K) | Bh(8K) | Bl(8K); rows are 64B, SWZ64.
// ---------------------------------------------------------------------------
__global__ __launch_bounds__(256, 2)
void k_gemm_mma()
{
    extern __shared__ char smem[];
    const uint32_t sb = smem_u32(smem);
    const int tid  = threadIdx.x;
    const int lane = tid & 31;
    const int wid  = tid >> 5;
    const int bm = blockIdx.y * BM;
    const int bn = blockIdx.x * BN;

    const int mbase = (wid >> 2) * 64;     // warp M offset (0 / 64)
    const int nbase = (wid & 3) * 32;      // warp N offset (0/32/64/96)

    const __nv_bfloat16* xh = g_xh  + (size_t)bm * KDIM;
    const __nv_bfloat16* xl = g_xl  + (size_t)bm * KDIM;
    const __nv_bfloat16* wh = g_Wth + (size_t)bn * KDIM;
    const __nv_bfloat16* wl = g_Wtl + (size_t)bn * KDIM;

    // per-chunk loader: 4 tiles x 128 rows x 4 vec16 = 2048 cp.async / CTA
    auto load_chunk = [&](int st, int c) {
        uint32_t base = sb + st * STAGE;
        size_t koff = (size_t)c * BKC;
#pragma unroll
        for (int it = 0; it < 2; it++) {
            int idx = tid + it * 256;
            int row = idx >> 2, v = idx & 3;
            uint32_t so = SWZ64(row * 64 + v * 16);
            size_t go = (size_t)row * KDIM + koff + v * 8;
            cp16(base +         so, xh + go);
            cp16(base +  8192 + so, xl + go);
            cp16(base + 16384 + so, wh + go);
            cp16(base + 24576 + so, wl + go);
        }
    };

    float acc[4][4][4];
#pragma unroll
    for (int i = 0; i < 4; i++)
#pragma unroll
        for (int j = 0; j < 4; j++)
#pragma unroll
            for (int r = 0; r < 4; r++) acc[i][j][r] = 0.f;

    load_chunk(0, 0);
    cp_commit();

    // precomputed ldmatrix lane addressing
    const int a_m = (lane & 15);              // row within m16 block
    const int a_h = (lane >> 4);              // k-half select
    const int b_n = ((lane >> 4) << 3) + (lane & 7);   // row within n16 block
    const int b_h = ((lane >> 3) & 1);        // k-half select

    for (int c = 0; c < NCH; c++) {
        if (c + 1 < NCH) { load_chunk((c + 1) & 1, c + 1); cp_commit(); }
        if (c + 1 < NCH) cp_wait<1>(); else cp_wait<0>();
        __syncthreads();

        uint32_t base = sb + (c & 1) * STAGE;
        uint32_t sAh = base;
        uint32_t sAl = base + 8192;
        uint32_t sBh = base + 16384;
        uint32_t sBl = base + 24576;

#pragma unroll
        for (int ks = 0; ks < 2; ks++) {
            uint32_t ah[4][4], bh[2][4], bl[2][4];
            int av = ks * 2 + a_h;
            int bv = ks * 2 + b_h;
#pragma unroll
            for (int mb = 0; mb < 4; mb++) {
                int m = mbase + mb * 16 + a_m;
                ldsm4(ah[mb], sAh + SWZ64(m * 64 + av * 16));
            }
#pragma unroll
            for (int nb2 = 0; nb2 < 2; nb2++) {
                int n = nbase + nb2 * 16 + b_n;
                uint32_t so = SWZ64(n * 64 + bv * 16);
                ldsm4(bh[nb2], sBh + so);
                ldsm4(bl[nb2], sBl + so);
            }
            // passes 1+2: Ah*Bh and Ah*Bl
#pragma unroll
            for (int mb = 0; mb < 4; mb++)
#pragma unroll
                for (int nb = 0; nb < 4; nb++) {
                    const uint32_t* fh = &bh[nb >> 1][(nb & 1) * 2];
                    const uint32_t* fl = &bl[nb >> 1][(nb & 1) * 2];
                    mma16816(acc[mb][nb], ah[mb], fh[0], fh[1]);
                    mma16816(acc[mb][nb], ah[mb], fl[0], fl[1]);
                }
            // pass 3: Al*Bh (load Al late to bound register pressure)
            uint32_t al[4][4];
#pragma unroll
            for (int mb = 0; mb < 4; mb++) {
                int m = mbase + mb * 16 + a_m;
                ldsm4(al[mb], sAl + SWZ64(m * 64 + av * 16));
            }
#pragma unroll
            for (int mb = 0; mb < 4; mb++)
#pragma unroll
                for (int nb = 0; nb < 4; nb++) {
                    const uint32_t* fh = &bh[nb >> 1][(nb & 1) * 2];
                    mma16816(acc[mb][nb], al[mb], fh[0], fh[1]);
                }
        }
        __syncthreads();
    }

    // Epilogue: bias + store (float2 per fragment half)
#pragma unroll
    for (int mb = 0; mb < 4; mb++) {
        int row = bm + mbase + mb * 16 + (lane >> 2);
#pragma unroll
        for (int nb = 0; nb < 4; nb++) {
            int col = bn + nbase + nb * 8 + (lane & 3) * 2;
            float b0 = g_bc[col], b1 = g_bc[col + 1];
            float2 v0 = make_float2(acc[mb][nb][0] + b0, acc[mb][nb][1] + b1);
            float2 v1 = make_float2(acc[mb][nb][2] + b0, acc[mb][nb][3] + b1);
            *(float2*)(g_QKVf + (size_t)row * NC + col) = v0;
            *(float2*)(g_QKVf + (size_t)(row + 8) * NC + col) = v1;
        }
    }
}

// ---------------------------------------------------------------------------
// Kernel C: per-token spectral attention + inverse eigen projection.
// ---------------------------------------------------------------------------
__global__ __launch_bounds__(256)
void k_attn(const float* __restrict__ E, float* __restrict__ out)
{
    __shared__ float sQ[KEIG][DH + 1];
    __shared__ float sK[KEIG][DH + 1];
    __shared__ float sV[KEIG][DH + 1];
    __shared__ float sS[KEIG][KEIG];
    __shared__ float sO[KEIG][DH + 1];
    __shared__ float sE[NH * KEIG];

    const int tok = blockIdx.x;
    const int tid = threadIdx.x;
    const float* row = g_QKVf + (size_t)tok * NC;

    for (int i = tid; i < KEIG * DH; i += 256) {
        int k = i >> 6, d = i & 63;
        sQ[k][d] = row[i];
        sK[k][d] = row[1024 + i];
        sV[k][d] = row[2048 + i];
    }
    sE[tid] = E[tid];
    __syncthreads();

    {
        int k = tid >> 4, l = tid & 15;
        float acc = 0.f;
#pragma unroll
        for (int d = 0; d < DH; d++)
            acc = fmaf(sQ[k][d], sK[l][d], acc);
        sS[k][l] = acc * 0.125f;
    }
    __syncthreads();

    if (tid < KEIG) {
        int k = tid;
        float m = sS[k][0];
#pragma unroll
        for (int l = 1; l < KEIG; l++) m = fmaxf(m, sS[k][l]);
        float e[KEIG];
        float sum = 0.f;
#pragma unroll
        for (int l = 0; l < KEIG; l++) { e[l] = __expf(sS[k][l] - m); sum += e[l]; }
        float inv = 1.f / sum;
#pragma unroll
        for (int l = 0; l < KEIG; l++) sS[k][l] = e[l] * inv;
    }
    __syncthreads();

    for (int i = tid; i < KEIG * DH; i += 256) {
        int k = i >> 6, d = i & 63;
        float acc = 0.f;
#pragma unroll
        for (int l = 0; l < KEIG; l++)
            acc = fmaf(sS[k][l], sV[l][d], acc);
        sO[k][d] = acc;
    }
    __syncthreads();

    float* orow = out + (size_t)tok * (NH * DH);
    for (int i = tid; i < NH * DH; i += 256) {
        int h = i >> 6, d = i & 63;
        float acc = 0.f;
#pragma unroll
        for (int k = 0; k < KEIG; k++)
            acc = fmaf(sE[h * KEIG + k], sO[k][d], acc);
        orow[i] = acc;
    }
}

// ---------------------------------------------------------------------------
extern "C" void kernel_launch(void* const* d_in, const int* in_sizes, int n_in,
                              void* d_out, int out_size)
{
    const float* x  = (const float*)d_in[0];
    const float* Wq = (const float*)d_in[1];
    const float* bq = (const float*)d_in[2];
    const float* Wk = (const float*)d_in[3];
    const float* bk = (const float*)d_in[4];
    const float* Wv = (const float*)d_in[5];
    const float* bv = (const float*)d_in[6];
    const float* E  = (const float*)d_in[7];
    const float* fw = (const float*)d_in[8];
    float* out = (float*)d_out;

    cudaFuncSetAttribute(k_gemm_mma, cudaFuncAttributeMaxDynamicSharedMemorySize,
                         GEMM_SMEM);

    k_transform_w<<<(KDIM * NC + 255) / 256, 256>>>(Wq, Wk, Wv, E, fw);
    k_transform_b<<<(NC + 255) / 256, 256>>>(bq, bk, bv, E, fw);
    k_split_x<<<(M_TOK * KDIM / 4) / 256, 256>>>(x);
    k_wsplit<<<dim3(NC / 32, KDIM / 32), 256>>>();
    k_gemm_mma<<<dim3(NC / BN, M_TOK / BM), 256, GEMM_SMEM>>>();
    k_attn<<<M_TOK, 256>>>(E, out);
}

// round 9
// speedup vs baseline: 2.8392x; 1.0715x over previous
#include <cuda_runtime.h>
#include <cuda_bf16.h>
#include <cstdint>

// Problem constants
#define D_MODEL 1024
#define NH      16
#define DH      64
#define KEIG    16
#define M_TOK   16384          // B * N = 4 * 4096
#define NC      3072           // 3 * NH * DH (fused Qf|Kf|Vf columns)
#define KDIM    1024

// GEMM tiling (mma.sync bf16 path)
#define BM 128
#define BN 128
#define BKC 32                 // K per chunk
#define NCH (KDIM / BKC)       // 32 chunks
#define STAGE 32768            // smem bytes per pipeline stage (4 tiles x 8KB)
#define GEMM_SMEM (2 * STAGE)  // 64 KB double buffered

// 64B-row swizzle: XOR 16B-vector index (bits 4:5) with row bits (bits 7:8)
#define SWZ64(o) ((uint32_t)(o) ^ ((((uint32_t)(o)) >> 3) & 0x30u))

// ---------------------------------------------------------------------------
// Device scratch (allocation-free rule: static __device__ arrays)
// ---------------------------------------------------------------------------
__device__ float         g_Wc[(size_t)KDIM * NC];    // eigen-folded weights fp32 [k][n]
__device__ float         g_bc[NC];                    // eigen-folded bias
__device__ float         g_QKVf[(size_t)M_TOK * NC]; // Qf|Kf|Vf per token
__device__ __nv_bfloat16 g_xh[(size_t)M_TOK * KDIM]; // x hi split  [m][k]
__device__ __nv_bfloat16 g_xl[(size_t)M_TOK * KDIM]; // x lo split
__device__ __nv_bfloat16 g_Wth[(size_t)NC * KDIM];   // W^T hi split [n][k]
__device__ __nv_bfloat16 g_Wtl[(size_t)NC * KDIM];   // W^T lo split

// ---------------------------------------------------------------------------
// PTX helpers (all baseline PTX — legal on non-'a' sm_103 target)
// ---------------------------------------------------------------------------
static __device__ __forceinline__ uint32_t smem_u32(const void* p) {
    uint32_t a;
    asm("{ .reg .u64 t; cvta.to.shared.u64 t, %1; cvt.u32.u64 %0, t; }"
        : "=r"(a) : "l"(p));
    return a;
}

static __device__ __forceinline__ void cp16(uint32_t saddr, const void* g) {
    asm volatile("cp.async.cg.shared.global [%0], [%1], 16;"
                 :: "r"(saddr), "l"(g));
}
static __device__ __forceinline__ void cp_commit() {
    asm volatile("cp.async.commit_group;" ::: "memory");
}
template <int N>
static __device__ __forceinline__ void cp_wait() {
    asm volatile("cp.async.wait_group %0;" :: "n"(N) : "memory");
}

static __device__ __forceinline__ void ldsm4(uint32_t* r, uint32_t addr) {
    asm volatile("ldmatrix.sync.aligned.m8n8.x4.shared.b16 {%0,%1,%2,%3}, [%4];"
                 : "=r"(r[0]), "=r"(r[1]), "=r"(r[2]), "=r"(r[3])
                 : "r"(addr));
}

static __device__ __forceinline__ void mma16816(float* d, const uint32_t* a,
                                                uint32_t b0, uint32_t b1) {
    asm volatile(
        "mma.sync.aligned.m16n8k16.row.col.f32.bf16.bf16.f32 "
        "{%0,%1,%2,%3}, {%4,%5,%6,%7}, {%8,%9}, {%0,%1,%2,%3};"
        : "+f"(d[0]), "+f"(d[1]), "+f"(d[2]), "+f"(d[3])
        : "r"(a[0]), "r"(a[1]), "r"(a[2]), "r"(a[3]), "r"(b0), "r"(b1));
}

// ---------------------------------------------------------------------------
// Kernel A1 (v2): fold eigenvectors + filter weights into fused weights.
// One block per (row r, matrix s). Stage W row (4KB) + E*fw in smem;
// each thread computes 4 k-outputs. ~16x less read traffic than v1.
// ---------------------------------------------------------------------------
__global__ __launch_bounds__(256)
void k_transform_w(const float* __restrict__ Wq,
                   const float* __restrict__ Wk,
                   const float* __restrict__ Wv,
                   const float* __restrict__ E,
                   const float* __restrict__ fw)
{
    __shared__ float Ws[1024];
    __shared__ float Ek[16][16];   // E[h][k] * fw[k]

    const int r = blockIdx.x;
    const int s = blockIdx.y;
    const int tid = threadIdx.x;
    const float* W = (s == 0) ? Wq : (s == 1) ? Wk : Wv;

    ((float4*)Ws)[tid] = ((const float4*)(W + (size_t)r * 1024))[tid];
    {
        int h = tid >> 4, k = tid & 15;
        Ek[h][k] = E[tid] * fw[k];
    }
    __syncthreads();

    const int d = tid & 63;
    float* dst = g_Wc + (size_t)r * NC + s * 1024;
#pragma unroll
    for (int j = 0; j < 4; j++) {
        int k = (tid >> 6) + j * 4;
        float acc = 0.f;
#pragma unroll
        for (int h = 0; h < NH; h++)
            acc = fmaf(Ek[h][k], Ws[h * 64 + d], acc);
        dst[k * 64 + d] = acc;
    }
}

__global__ void k_transform_b(const float* __restrict__ bq,
                              const float* __restrict__ bk,
                              const float* __restrict__ bv,
                              const float* __restrict__ E,
                              const float* __restrict__ fw)
{
    int j = blockIdx.x * blockDim.x + threadIdx.x;
    if (j >= NC) return;
    int s = j >> 10;
    int c = j & 1023;
    int k = c >> 6;
    int d = c & 63;
    const float* b = (s == 0) ? bq : (s == 1) ? bk : bv;
    float acc = 0.f;
#pragma unroll
    for (int h = 0; h < NH; h++)
        acc = fmaf(E[h * KEIG + k], b[h * DH + d], acc);
    g_bc[j] = acc * fw[k];
}

// ---------------------------------------------------------------------------
// Kernel A2: split x into bf16 hi/lo (same [m][k] layout)
// ---------------------------------------------------------------------------
__global__ __launch_bounds__(256)
void k_split_x(const float* __restrict__ x)
{
    size_t i = ((size_t)blockIdx.x * 256 + threadIdx.x) * 4;
    float4 v = *(const float4*)(x + i);
    __nv_bfloat16 h0 = __float2bfloat16(v.x);
    __nv_bfloat16 h1 = __float2bfloat16(v.y);
    __nv_bfloat16 h2 = __float2bfloat16(v.z);
    __nv_bfloat16 h3 = __float2bfloat16(v.w);
    __nv_bfloat16 l0 = __float2bfloat16(v.x - __bfloat162float(h0));
    __nv_bfloat16 l1 = __float2bfloat16(v.y - __bfloat162float(h1));
    __nv_bfloat16 l2 = __float2bfloat16(v.z - __bfloat162float(h2));
    __nv_bfloat16 l3 = __float2bfloat16(v.w - __bfloat162float(h3));
    uint2 ph, pl;
    ph.x = ((uint32_t)__bfloat16_as_ushort(h1) << 16) | __bfloat16_as_ushort(h0);
    ph.y = ((uint32_t)__bfloat16_as_ushort(h3) << 16) | __bfloat16_as_ushort(h2);
    pl.x = ((uint32_t)__bfloat16_as_ushort(l1) << 16) | __bfloat16_as_ushort(l0);
    pl.y = ((uint32_t)__bfloat16_as_ushort(l3) << 16) | __bfloat16_as_ushort(l2);
    *(uint2*)(g_xh + i) = ph;
    *(uint2*)(g_xl + i) = pl;
}

// ---------------------------------------------------------------------------
// Kernel A3: transpose g_Wc [k][n] -> bf16 hi/lo [n][k] (smem-tiled)
// ---------------------------------------------------------------------------
__global__ __launch_bounds__(256)
void k_wsplit()
{
    __shared__ float t[32][33];
    int tx = threadIdx.x & 31;
    int ty = threadIdx.x >> 5;       // 0..7
    int n0 = blockIdx.x * 32;
    int k0 = blockIdx.y * 32;
#pragma unroll
    for (int i = 0; i < 32; i += 8)
        t[ty + i][tx] = g_Wc[(size_t)(k0 + ty + i) * NC + (n0 + tx)];
    __syncthreads();
#pragma unroll
    for (int i = 0; i < 32; i += 8) {
        int n = n0 + ty + i;
        int k = k0 + tx;
        float v = t[tx][ty + i];
        __nv_bfloat16 h = __float2bfloat16(v);
        __nv_bfloat16 l = __float2bfloat16(v - __bfloat162float(h));
        g_Wth[(size_t)n * KDIM + k] = h;
        g_Wtl[(size_t)n * KDIM + k] = l;
    }
}

// ---------------------------------------------------------------------------
// Kernel B: bf16-split GEMM via mma.sync (HMMA), cp.async double buffered.
//   QKVf[16384, 3072] = x @ Wc + bc  ==  xh*Wh + xh*Wl + xl*Wh (fp32 accum)
// CTA 128x128, 8 warps (2x4), warp tile 64x32, BK=32.  (unchanged, at HMMA peak)
// ---------------------------------------------------------------------------
__global__ __launch_bounds__(256, 2)
void k_gemm_mma()
{
    extern __shared__ char smem[];
    const uint32_t sb = smem_u32(smem);
    const int tid  = threadIdx.x;
    const int lane = tid & 31;
    const int wid  = tid >> 5;
    const int bm = blockIdx.y * BM;
    const int bn = blockIdx.x * BN;

    const int mbase = (wid >> 2) * 64;
    const int nbase = (wid & 3) * 32;

    const __nv_bfloat16* xh = g_xh  + (size_t)bm * KDIM;
    const __nv_bfloat16* xl = g_xl  + (size_t)bm * KDIM;
    const __nv_bfloat16* wh = g_Wth + (size_t)bn * KDIM;
    const __nv_bfloat16* wl = g_Wtl + (size_t)bn * KDIM;

    auto load_chunk = [&](int st, int c) {
        uint32_t base = sb + st * STAGE;
        size_t koff = (size_t)c * BKC;
#pragma unroll
        for (int it = 0; it < 2; it++) {
            int idx = tid + it * 256;
            int row = idx >> 2, v = idx & 3;
            uint32_t so = SWZ64(row * 64 + v * 16);
            size_t go = (size_t)row * KDIM + koff + v * 8;
            cp16(base +         so, xh + go);
            cp16(base +  8192 + so, xl + go);
            cp16(base + 16384 + so, wh + go);
            cp16(base + 24576 + so, wl + go);
        }
    };

    float acc[4][4][4];
#pragma unroll
    for (int i = 0; i < 4; i++)
#pragma unroll
        for (int j = 0; j < 4; j++)
#pragma unroll
            for (int r = 0; r < 4; r++) acc[i][j][r] = 0.f;

    load_chunk(0, 0);
    cp_commit();

    const int a_m = (lane & 15);
    const int a_h = (lane >> 4);
    const int b_n = ((lane >> 4) << 3) + (lane & 7);
    const int b_h = ((lane >> 3) & 1);

    for (int c = 0; c < NCH; c++) {
        if (c + 1 < NCH) { load_chunk((c + 1) & 1, c + 1); cp_commit(); }
        if (c + 1 < NCH) cp_wait<1>(); else cp_wait<0>();
        __syncthreads();

        uint32_t base = sb + (c & 1) * STAGE;
        uint32_t sAh = base;
        uint32_t sAl = base + 8192;
        uint32_t sBh = base + 16384;
        uint32_t sBl = base + 24576;

#pragma unroll
        for (int ks = 0; ks < 2; ks++) {
            uint32_t ah[4][4], bh[2][4], bl[2][4];
            int av = ks * 2 + a_h;
            int bv = ks * 2 + b_h;
#pragma unroll
            for (int mb = 0; mb < 4; mb++) {
                int m = mbase + mb * 16 + a_m;
                ldsm4(ah[mb], sAh + SWZ64(m * 64 + av * 16));
            }
#pragma unroll
            for (int nb2 = 0; nb2 < 2; nb2++) {
                int n = nbase + nb2 * 16 + b_n;
                uint32_t so = SWZ64(n * 64 + bv * 16);
                ldsm4(bh[nb2], sBh + so);
                ldsm4(bl[nb2], sBl + so);
            }
#pragma unroll
            for (int mb = 0; mb < 4; mb++)
#pragma unroll
                for (int nb = 0; nb < 4; nb++) {
                    const uint32_t* fh = &bh[nb >> 1][(nb & 1) * 2];
                    const uint32_t* fl = &bl[nb >> 1][(nb & 1) * 2];
                    mma16816(acc[mb][nb], ah[mb], fh[0], fh[1]);
                    mma16816(acc[mb][nb], ah[mb], fl[0], fl[1]);
                }
            uint32_t al[4][4];
#pragma unroll
            for (int mb = 0; mb < 4; mb++) {
                int m = mbase + mb * 16 + a_m;
                ldsm4(al[mb], sAl + SWZ64(m * 64 + av * 16));
            }
#pragma unroll
            for (int mb = 0; mb < 4; mb++)
#pragma unroll
                for (int nb = 0; nb < 4; nb++) {
                    const uint32_t* fh = &bh[nb >> 1][(nb & 1) * 2];
                    mma16816(acc[mb][nb], al[mb], fh[0], fh[1]);
                }
        }
        __syncthreads();
    }

#pragma unroll
    for (int mb = 0; mb < 4; mb++) {
        int row = bm + mbase + mb * 16 + (lane >> 2);
#pragma unroll
        for (int nb = 0; nb < 4; nb++) {
            int col = bn + nbase + nb * 8 + (lane & 3) * 2;
            float b0 = g_bc[col], b1 = g_bc[col + 1];
            float2 v0 = make_float2(acc[mb][nb][0] + b0, acc[mb][nb][1] + b1);
            float2 v1 = make_float2(acc[mb][nb][2] + b0, acc[mb][nb][3] + b1);
            *(float2*)(g_QKVf + (size_t)row * NC + col) = v0;
            *(float2*)(g_QKVf + (size_t)(row + 8) * NC + col) = v1;
        }
    }
}

// ---------------------------------------------------------------------------
// Kernel C (v2): per-token spectral attention, 2 tokens/block, float4 smem ops.
// Row pad = 68 floats (16B-aligned rows, odd vec4 stride -> spread banks).
// ---------------------------------------------------------------------------
#define TPB 2
__global__ __launch_bounds__(256)
void k_attn(const float* __restrict__ E, float* __restrict__ out)
{
    __shared__ float sQ[TPB][KEIG][68];
    __shared__ float sK[TPB][KEIG][68];
    __shared__ float sV[TPB][KEIG][68];
    __shared__ float sS[TPB][KEIG][17];
    __shared__ float sO[TPB][KEIG][68];
    __shared__ float sE[NH * KEIG];

    const int tid  = threadIdx.x;
    const int tok0 = blockIdx.x * TPB;

    // Load 2 tokens x 3 x 1024 floats = 1536 float4, 6 per thread.
#pragma unroll
    for (int v = tid; v < TPB * 768; v += 256) {
        int t = v / 768;
        int r = v - t * 768;
        int mat = r >> 8;             // 0=Q 1=K 2=V
        int e   = r & 255;            // vec4 index within 16x64
        int k = e >> 4, dv = e & 15;
        float4 val = ((const float4*)(g_QKVf + (size_t)(tok0 + t) * NC + mat * 1024))[e];
        float* dst = (mat == 0) ? &sQ[t][k][dv * 4]
                   : (mat == 1) ? &sK[t][k][dv * 4]
                                : &sV[t][k][dv * 4];
        *(float4*)dst = val;
    }
    sE[tid] = E[tid];
    __syncthreads();

    // Scores: 2 pairs per thread (512 total). float4 dot over 64 dims.
    {
        int t = tid >> 7;
        int u = tid & 127;
#pragma unroll
        for (int pp = 0; pp < 2; pp++) {
            int p = u + pp * 128;
            int k = p >> 4, l = p & 15;
            float acc = 0.f;
#pragma unroll
            for (int dv = 0; dv < 16; dv++) {
                float4 q = *(const float4*)&sQ[t][k][dv * 4];
                float4 c = *(const float4*)&sK[t][l][dv * 4];
                acc = fmaf(q.x, c.x, acc);
                acc = fmaf(q.y, c.y, acc);
                acc = fmaf(q.z, c.z, acc);
                acc = fmaf(q.w, c.w, acc);
            }
            sS[t][k][l] = acc * 0.125f;    // 1/sqrt(64)
        }
    }
    __syncthreads();

    // Softmax: 32 rows, one per thread.
    if (tid < TPB * KEIG) {
        int t = tid >> 4, k = tid & 15;
        float m = sS[t][k][0];
#pragma unroll
        for (int l = 1; l < KEIG; l++) m = fmaxf(m, sS[t][k][l]);
        float e[KEIG];
        float sum = 0.f;
#pragma unroll
        for (int l = 0; l < KEIG; l++) { e[l] = __expf(sS[t][k][l] - m); sum += e[l]; }
        float inv = 1.f / sum;
#pragma unroll
        for (int l = 0; l < KEIG; l++) sS[t][k][l] = e[l] * inv;
    }
    __syncthreads();

    // out_f[k][d] = sum_l attn[k][l] * Vf[l][d]; 2 vec4-outputs per thread.
    {
        int t = tid >> 7;
        int u = tid & 127;
#pragma unroll
        for (int pp = 0; pp < 2; pp++) {
            int p = u + pp * 128;
            int k = p >> 4, dv = p & 15;
            float4 acc = make_float4(0.f, 0.f, 0.f, 0.f);
#pragma unroll
            for (int l = 0; l < KEIG; l++) {
                float a = sS[t][k][l];
                float4 v = *(const float4*)&sV[t][l][dv * 4];
                acc.x = fmaf(a, v.x, acc.x);
                acc.y = fmaf(a, v.y, acc.y);
                acc.z = fmaf(a, v.z, acc.z);
                acc.w = fmaf(a, v.w, acc.w);
            }
            *(float4*)&sO[t][k][dv * 4] = acc;
        }
    }
    __syncthreads();

    // out[h][d] = sum_k E[h,k] * out_f[k][d]; write straight to gmem.
    {
        int t = tid >> 7;
        int u = tid & 127;
#pragma unroll
        for (int pp = 0; pp < 2; pp++) {
            int p = u + pp * 128;
            int h = p >> 4, dv = p & 15;
            float4 acc = make_float4(0.f, 0.f, 0.f, 0.f);
#pragma unroll
            for (int k = 0; k < KEIG; k++) {
                float a = sE[h * KEIG + k];
                float4 v = *(const float4*)&sO[t][k][dv * 4];
                acc.x = fmaf(a, v.x, acc.x);
                acc.y = fmaf(a, v.y, acc.y);
                acc.z = fmaf(a, v.z, acc.z);
                acc.w = fmaf(a, v.w, acc.w);
            }
            ((float4*)(out + (size_t)(tok0 + t) * (NH * DH)))[h * 16 + dv] = acc;
        }
    }
}

// ---------------------------------------------------------------------------
extern "C" void kernel_launch(void* const* d_in, const int* in_sizes, int n_in,
                              void* d_out, int out_size)
{
    const float* x  = (const float*)d_in[0];
    const float* Wq = (const float*)d_in[1];
    const float* bq = (const float*)d_in[2];
    const float* Wk = (const float*)d_in[3];
    const float* bk = (const float*)d_in[4];
    const float* Wv = (const float*)d_in[5];
    const float* bv = (const float*)d_in[6];
    const float* E  = (const float*)d_in[7];
    const float* fw = (const float*)d_in[8];
    float* out = (float*)d_out;

    cudaFuncSetAttribute(k_gemm_mma, cudaFuncAttributeMaxDynamicSharedMemorySize,
                         GEMM_SMEM);

    k_transform_w<<<dim3(KDIM, 3), 256>>>(Wq, Wk, Wv, E, fw);
    k_transform_b<<<(NC + 255) / 256, 256>>>(bq, bk, bv, E, fw);
    k_split_x<<<(M_TOK * KDIM / 4) / 256, 256>>>(x);
    k_wsplit<<<dim3(NC / 32, KDIM / 32), 256>>>();
    k_gemm_mma<<<dim3(NC / BN, M_TOK / BM), 256, GEMM_SMEM>>>();
    k_attn<<<M_TOK / TPB, 256>>>(E, out);
}